// round 16
// baseline (speedup 1.0000x reference)
#include <cuda_runtime.h>
#include <cuda_bf16.h>
#include <cuda_fp16.h>
#include <mma.h>
#include <math.h>
#include <stdint.h>

using namespace nvcuda;

#define MAXN 4096
#define D    128

// ---------------- scratch (device globals; no allocation allowed) -------------
__device__ __half        g_S[(size_t)MAXN * MAXN]; // exp(sim/tau) in fp16, masked = 0
__device__ __nv_bfloat16 g_hn[MAXN * D];           // normalized hard_neg rows (bf16)
__device__ float         g_pos[MAXN];              // exp(cos(hp_x, hp_qx)/tau)
__device__ float         g_loss[MAXN];
__device__ int           g_q[MAXN];                // positive-pair partner

// ---------------- K1: prep (indexed by pair-row; also builds g_q) --------------
// pp row r = (x, qx); pi spans all N exactly once, so grid=npairs covers all x.
__global__ void prep_kernel(const float* __restrict__ emb,
                            const int* __restrict__ pp, int N) {
    int r = blockIdx.x;
    int x  = pp[2 * r];
    int qx = pp[2 * r + 1];
    int d = threadIdx.x;
    int fx = N - 1;
    while (fx == x || fx == qx) fx--;   // largest index not in {x, q[x]}

    float a  = emb[(size_t)x  * D + d];
    float b  = emb[(size_t)qx * D + d];
    float pf = emb[(size_t)fx * D + d];
    float h  = 0.5f * (a + pf);

    float v0 = h * h, v1 = a * a, v2 = b * b, v3 = a * b;
    __shared__ float sh[4][4];
    int lane = d & 31, w = d >> 5;
    #pragma unroll
    for (int o = 16; o; o >>= 1) {
        v0 += __shfl_xor_sync(0xffffffffu, v0, o);
        v1 += __shfl_xor_sync(0xffffffffu, v1, o);
        v2 += __shfl_xor_sync(0xffffffffu, v2, o);
        v3 += __shfl_xor_sync(0xffffffffu, v3, o);
    }
    if (lane == 0) { sh[0][w] = v0; sh[1][w] = v1; sh[2][w] = v2; sh[3][w] = v3; }
    __syncthreads();
    float nn = sh[0][0] + sh[0][1] + sh[0][2] + sh[0][3];
    float inv = 1.0f / fmaxf(sqrtf(nn), 1e-8f);
    g_hn[(size_t)x * D + d] = __float2bfloat16(h * inv);

    if (d == 0) {
        g_q[x] = qx;                    // partner map (consumed by gemm, next launch)
        float aa = sh[1][0] + sh[1][1] + sh[1][2] + sh[1][3];
        float bb = sh[2][0] + sh[2][1] + sh[2][2] + sh[2][3];
        float ab = sh[3][0] + sh[3][1] + sh[3][2] + sh[3][3];
        float dot = 2.5f * ab - 0.75f * (aa + bb);
        float nxx = 2.25f * aa + 0.25f * bb - 1.5f * ab;
        float nyy = 2.25f * bb + 0.25f * aa - 1.5f * ab;
        float nx = fmaxf(sqrtf(nxx), 1e-8f);
        float ny = fmaxf(sqrtf(nyy), 1e-8f);
        g_pos[x] = expf((dot / (nx * ny)) * 5.0f);
    }
}

// ---------------- K2: WMMA bf16 GEMM + exp + mask (fp16 out, TRIANGLE) ---------
// 128x128 tile per CTA, upper triangle only (528 CTAs), mirror store.
// K chunked 2x64 (KP=72 pad, conflict-free ldmatrix); tiles 36.9KB, staging
// 67.6KB reuses tile space -> 67584 B/CTA -> 3 CTAs/SM.
#define KP  72
#define TSZ (128 * KP)       // bf16 elements per tile
#define LDS 132              // staging row stride (floats); 528B = 33*16B -> legal

__global__ void __launch_bounds__(256, 3) gemm_wmma_kernel(int N) {
    extern __shared__ char smem[];
    __nv_bfloat16* Ah = (__nv_bfloat16*)smem;
    __nv_bfloat16* Bh = Ah + TSZ;
    float* Tst = (float*)smem;          // epilogue staging 128 x LDS (reuses tiles)
    __shared__ int s_qa[128];           // q[m0 + r]
    __shared__ int s_qb[128];           // q[n0 + c]

    int nb = N >> 7;
    int bid = blockIdx.x;
    int bi = 0, rem = bid;
    while (rem >= nb - bi) { rem -= nb - bi; bi++; }
    int bj = bi + rem;                  // bj >= bi
    int m0 = bi * 128, n0 = bj * 128;

    int tid = threadIdx.x, wid = tid >> 5;
    int wm = wid >> 1, wn = wid & 1;    // warp tile: rows wm*32..+32, cols wn*64..+64

    if (tid < 128)      s_qa[tid]       = g_q[m0 + tid];
    else                s_qb[tid - 128] = g_q[n0 + (tid - 128)];

    wmma::fragment<wmma::accumulator, 16, 16, 16, float> acc[2][4];
    #pragma unroll
    for (int i = 0; i < 2; ++i)
        #pragma unroll
        for (int j = 0; j < 4; ++j) wmma::fill_fragment(acc[i][j], 0.0f);

    #pragma unroll
    for (int ch = 0; ch < 2; ++ch) {
        const __nv_bfloat16* srcA = g_hn + (size_t)bi * 128 * D + ch * 64;
        const __nv_bfloat16* srcB = g_hn + (size_t)bj * 128 * D + ch * 64;
        #pragma unroll
        for (int i = tid; i < 1024; i += 256) {   // 1024 uint4 per tile
            int row = i >> 3, c8 = i & 7;
            *(uint4*)(Ah + row * KP + c8 * 8) = *(const uint4*)(srcA + (size_t)row * D + c8 * 8);
            *(uint4*)(Bh + row * KP + c8 * 8) = *(const uint4*)(srcB + (size_t)row * D + c8 * 8);
        }
        __syncthreads();

        #pragma unroll
        for (int ks = 0; ks < 4; ++ks) {
            wmma::fragment<wmma::matrix_a, 16, 16, 16, __nv_bfloat16, wmma::row_major> a_f[2];
            #pragma unroll
            for (int i = 0; i < 2; ++i)
                wmma::load_matrix_sync(a_f[i], Ah + (wm * 32 + i * 16) * KP + ks * 16, KP);
            #pragma unroll
            for (int j = 0; j < 4; ++j) {
                wmma::fragment<wmma::matrix_b, 16, 16, 16, __nv_bfloat16, wmma::col_major> b_f;
                wmma::load_matrix_sync(b_f, Bh + (wn * 64 + j * 16) * KP + ks * 16, KP);
                wmma::mma_sync(acc[0][j], a_f[0], b_f, acc[0][j]);
                wmma::mma_sync(acc[1][j], a_f[1], b_f, acc[1][j]);
            }
        }
        __syncthreads();
    }

    // stage raw accumulators to smem (ldm = 132 floats = 528B, multiple of 16B)
    #pragma unroll
    for (int i = 0; i < 2; ++i)
        #pragma unroll
        for (int j = 0; j < 4; ++j)
            wmma::store_matrix_sync(Tst + (wm * 32 + i * 16) * LDS + wn * 64 + j * 16,
                                    acc[i][j], LDS, wmma::mem_row_major);
    __syncthreads();

    // direct store: thread -> 8 consecutive cols of one row; fused mask+exp; STG.128
    {
        int rbase = tid >> 4;            // 0..15
        int c8 = (tid & 15) * 8;         // 0,8,..,120
        #pragma unroll
        for (int p = 0; p < 8; ++p) {
            int r = p * 16 + rbase;
            int m = m0 + r, qm = s_qa[r];
            const float* src = Tst + r * LDS + c8;
            unsigned pkw[4];
            #pragma unroll
            for (int h2 = 0; h2 < 4; ++h2) {
                int n_a = n0 + c8 + 2 * h2, n_b = n_a + 1;
                float fa = (n_a == m || n_a == qm) ? 0.0f : __expf(src[2 * h2]     * 5.0f);
                float fb = (n_b == m || n_b == qm) ? 0.0f : __expf(src[2 * h2 + 1] * 5.0f);
                __half2 hh = __floats2half2_rn(fa, fb);
                pkw[h2] = *(unsigned*)&hh;
            }
            *(uint4*)(g_S + (size_t)m * N + n0 + c8) =
                make_uint4(pkw[0], pkw[1], pkw[2], pkw[3]);
        }
    }
    // mirror store: thread owns staging column c; gathers 8 rows; fused mask+exp
    {
        int c    = tid & 127;
        int hseg = tid >> 7;             // 0/1 -> r halves
        int nrow = n0 + c, qn = s_qb[c];
        #pragma unroll
        for (int j = 0; j < 8; ++j) {
            int r0 = hseg * 64 + j * 8;
            unsigned pkw[4];
            #pragma unroll
            for (int h2 = 0; h2 < 4; ++h2) {
                int m_a = m0 + r0 + 2 * h2, m_b = m_a + 1;
                float fa = (m_a == nrow || m_a == qn) ? 0.0f
                         : __expf(Tst[(r0 + 2 * h2)     * LDS + c] * 5.0f);
                float fb = (m_b == nrow || m_b == qn) ? 0.0f
                         : __expf(Tst[(r0 + 2 * h2 + 1) * LDS + c] * 5.0f);
                __half2 hh = __floats2half2_rn(fa, fb);
                pkw[h2] = *(unsigned*)&hh;
            }
            *(uint4*)(g_S + (size_t)nrow * N + m0 + r0) =
                make_uint4(pkw[0], pkw[1], pkw[2], pkw[3]);
        }
    }
}

// ---------------- K3 helper: scan 8 privatized histogram copies ----------------
__device__ __forceinline__ void locate_bin256x8(unsigned* hist, unsigned k,
                                                unsigned* s_warp, int* s_bin, int* s_krem) {
    int tid = threadIdx.x;
    unsigned local = 0;
    #pragma unroll
    for (int i = 0; i < 8; ++i) local += hist[tid + 256 * i];
    unsigned inc = local;
    int lane = tid & 31, w = tid >> 5;
    #pragma unroll
    for (int o = 1; o < 32; o <<= 1) {
        unsigned t = __shfl_up_sync(0xffffffffu, inc, o);
        if (lane >= o) inc += t;
    }
    if (lane == 31) s_warp[w] = inc;
    __syncthreads();
    unsigned woff = 0;
    for (int ww = 0; ww < w; ++ww) woff += s_warp[ww];
    unsigned excl = woff + inc - local;
    if (excl <= k && k < excl + local) { *s_bin = tid; *s_krem = (int)(k - excl); }
    __syncthreads();
}

// ---------------- K3: per-row exact radix select + thresholded sum (fp16) ------
// R11 version, byte-identical (measured best: 25.0us). FROZEN.
__global__ void __launch_bounds__(256) select_kernel(const int* __restrict__ stage_ptr,
                                                     int N, int rank) {
    __shared__ unsigned hist[2048];     // 8 warp-private copies of 256 bins
    __shared__ unsigned s_warp[8];
    __shared__ int      s_bin, s_krem;
    __shared__ float    s_red[8];

    int x = blockIdx.x, tid = threadIdx.x, wid = tid >> 5;
    const uint4* row16 = (const uint4*)(g_S + (size_t)x * N);   // 8 fp16 per uint4
    uint4 p0 = row16[tid];
    uint4 p1 = row16[tid + 256];
    unsigned pk[8] = {p0.x, p0.y, p0.z, p0.w, p1.x, p1.y, p1.z, p1.w};

    int stage = *stage_ptr;
    float ssum = 0.0f;
    unsigned hbase = (unsigned)wid << 8;

    if (stage) {
        // ---- L0: fp16 bits [15:8] ----
        #pragma unroll
        for (int i = 0; i < 8; ++i) hist[tid + 256 * i] = 0;
        __syncthreads();
        #pragma unroll
        for (int r = 0; r < 8; ++r) {
            atomicAdd(&hist[hbase + ((pk[r] >> 8)  & 0xffu)], 1u);
            atomicAdd(&hist[hbase + ((pk[r] >> 24) & 0xffu)], 1u);
        }
        __syncthreads();
        locate_bin256x8(hist, (unsigned)rank, s_warp, &s_bin, &s_krem);
        unsigned b0 = (unsigned)s_bin;
        unsigned k1 = (unsigned)s_krem;
        __syncthreads();

        // ---- L1: fp16 bits [7:0] within bin b0 ----
        #pragma unroll
        for (int i = 0; i < 8; ++i) hist[tid + 256 * i] = 0;
        __syncthreads();
        #pragma unroll
        for (int r = 0; r < 8; ++r) {
            unsigned lo = pk[r] & 0xffffu, hi = pk[r] >> 16;
            if ((lo >> 8) == b0) atomicAdd(&hist[hbase + (lo & 0xffu)], 1u);
            if ((hi >> 8) == b0) atomicAdd(&hist[hbase + (hi & 0xffu)], 1u);
        }
        __syncthreads();
        locate_bin256x8(hist, k1, s_warp, &s_bin, &s_krem);
        unsigned tbits = (b0 << 8) | (unsigned)s_bin;   // exact rank-th fp16 value

        #pragma unroll
        for (int r = 0; r < 8; ++r) {
            unsigned lo = pk[r] & 0xffffu, hi = pk[r] >> 16;
            if (lo >= tbits) ssum += __half2float(__ushort_as_half((unsigned short)lo));
            if (hi >= tbits) ssum += __half2float(__ushort_as_half((unsigned short)hi));
        }
    } else {
        #pragma unroll
        for (int r = 0; r < 8; ++r) {
            ssum += __half2float(__ushort_as_half((unsigned short)(pk[r] & 0xffffu)));
            ssum += __half2float(__ushort_as_half((unsigned short)(pk[r] >> 16)));
        }
    }

    int lane = tid & 31, w = tid >> 5;
    #pragma unroll
    for (int o = 16; o; o >>= 1) ssum += __shfl_xor_sync(0xffffffffu, ssum, o);
    if (lane == 0) s_red[w] = ssum;
    __syncthreads();
    if (tid == 0) {
        float tot = 0.0f;
        #pragma unroll
        for (int ww = 0; ww < 8; ++ww) tot += s_red[ww];
        float pos = g_pos[x];
        g_loss[x] = -logf(pos / (pos + tot));
    }
}

// ---------------- K4: deterministic mean reduce --------------------------------
__global__ void reduce_kernel(float* __restrict__ out, int N) {
    __shared__ float s_red[8];
    int tid = threadIdx.x;
    float s = 0.0f;
    for (int i = tid; i < N; i += 256) s += g_loss[i];
    int lane = tid & 31, w = tid >> 5;
    #pragma unroll
    for (int o = 16; o; o >>= 1) s += __shfl_xor_sync(0xffffffffu, s, o);
    if (lane == 0) s_red[w] = s;
    __syncthreads();
    if (tid == 0) {
        float tot = 0.0f;
        #pragma unroll
        for (int ww = 0; ww < 8; ++ww) tot += s_red[ww];
        out[0] = tot / (float)N;
    }
}

// ---------------- launch --------------------------------------------------------
extern "C" void kernel_launch(void* const* d_in, const int* in_sizes, int n_in,
                              void* d_out, int out_size) {
    const float* emb   = (const float*)d_in[0];
    const int*   pp    = (const int*)d_in[1];
    const int*   stage = (const int*)d_in[2];

    int N      = in_sizes[0] / D;        // 4096
    int npairs = in_sizes[1] / 2;        // 4096

    prep_kernel<<<npairs, D>>>(emb, pp, N);   // builds g_q + g_hn + g_pos

    int nb   = N >> 7;
    int nblk = nb * (nb + 1) / 2;        // upper triangle
    int smem = 128 * LDS * 4;            // 67584 bytes (tiles fit inside)
    cudaFuncSetAttribute(gemm_wmma_kernel,
                         cudaFuncAttributeMaxDynamicSharedMemorySize, smem);
    gemm_wmma_kernel<<<nblk, 256, smem>>>(N);

    int rank = (int)(0.8 * (double)(N - 1) + 1e-9);   // 3276 for N=4096
    select_kernel<<<N, 256>>>(stage, N, rank);

    reduce_kernel<<<1, 256>>>((float*)d_out, N);
}